// round 4
// baseline (speedup 1.0000x reference)
#include <cuda_runtime.h>
#include <cuda_fp16.h>
#include <cstdint>
#include <cstddef>

// ============================================================
// Problem dims (fixed)
// ============================================================
#define MROWS 8192
#define NDIM  4096
#define KDIM  4096

// GEMM tiling
#define TM 128
#define TN 256
#define KB 64                        // K halfs per stage (128 B per row)
#define NKB (KDIM / KB)              // 64
#define NSTAGES 4
#define A_BYTES (TM * 128)           // 16384
#define B_BYTES (TN * 128)           // 32768
#define STAGE_BYTES (A_BYTES + B_BYTES)          // 49152
#define GEMM_SMEM (NSTAGES * STAGE_BYTES)        // 196608

#define THREADS 512                  // 16 warps; warp grid 2 (M) x 8 (N); warp tile 64x32

// ============================================================
// Scratch (static __device__ — no runtime allocation)
// ============================================================
__device__ __half g_XA[(size_t)MROWS * KDIM];  // 64 MB: (qx - zx) exact ints in fp16
__device__ __half g_WB[(size_t)NDIM * KDIM];   // 32 MB: dequantized weights in fp16
__device__ float  g_SX[MROWS];                 // per-row activation scale

// ============================================================
// PTX helpers (sm_100 baseline ISA only — NO tcgen05; the harness
// builds for plain sm_100 where 'a'-suffix features are unavailable)
// ============================================================
__device__ __forceinline__ uint32_t smem_u32(const void* p) {
    uint32_t a;
    asm("{ .reg .u64 t; cvta.to.shared.u64 t, %1; cvt.u32.u64 %0, t; }" : "=r"(a) : "l"(p));
    return a;
}

#define CP16(smem_addr, gptr) \
    asm volatile("cp.async.cg.shared.global [%0], [%1], 16;" :: "r"(smem_addr), "l"(gptr) : "memory")
#define CP_COMMIT()  asm volatile("cp.async.commit_group;" ::: "memory")
#define CP_WAIT2()   asm volatile("cp.async.wait_group 2;" ::: "memory")
#define CP_WAIT0()   asm volatile("cp.async.wait_group 0;" ::: "memory")

#define LDSM_X4(r0, r1, r2, r3, addr)                                        \
    asm volatile("ldmatrix.sync.aligned.m8n8.x4.shared.b16 {%0,%1,%2,%3}, [%4];" \
                 : "=r"(r0), "=r"(r1), "=r"(r2), "=r"(r3) : "r"(addr))

#define MMA16816(c, a, b)                                                    \
    asm volatile("mma.sync.aligned.m16n8k16.row.col.f32.f16.f16.f32 "        \
                 "{%0,%1,%2,%3}, {%4,%5,%6,%7}, {%8,%9}, {%0,%1,%2,%3};"     \
                 : "+f"((c)[0]), "+f"((c)[1]), "+f"((c)[2]), "+f"((c)[3])    \
                 : "r"((a)[0]), "r"((a)[1]), "r"((a)[2]), "r"((a)[3]),       \
                   "r"((b)[0]), "r"((b)[1]))

// One K-block stage load (plain macro; no device lambda).
// A rows {r0, r0+64}, B rows {r0, +64, +128, +192}; one 16B chunk per row.
#define LOAD_STAGE(kb)                                                        \
    do {                                                                      \
        const uint32_t so = (uint32_t)((kb) & (NSTAGES - 1)) * STAGE_BYTES;   \
        const char* pA = gA + (size_t)(kb) * 128;                             \
        const char* pB = gB + (size_t)(kb) * 128;                             \
        CP16(smA + so,             pA);                                       \
        CP16(smA + so + 64 * 128,  pA + (size_t)64 * KDIM * 2);               \
        CP16(smB + so,             pB);                                       \
        CP16(smB + so + 64 * 128,  pB + (size_t)64 * KDIM * 2);               \
        CP16(smB + so + 128 * 128, pB + (size_t)128 * KDIM * 2);              \
        CP16(smB + so + 192 * 128, pB + (size_t)192 * KDIM * 2);              \
        CP_COMMIT();                                                          \
    } while (0)

// ============================================================
// Kernel 1: weight group quant-dequant -> fp16 (gs=128, nbit=4, asym)
// scale=(max-min)/15, z=-8-rint(min/s), q=clip(rint(w/s)+z,-8,7), deq=(q-z)*s
// ============================================================
__global__ void __launch_bounds__(256) w_quant_kernel(const float* __restrict__ w) {
    int g    = blockIdx.x * 8 + (threadIdx.x >> 5);
    int lane = threadIdx.x & 31;
    const float* wg = w + (size_t)g * 128;

    float v[4];
    float mn = 3.4e38f, mx = -3.4e38f;
#pragma unroll
    for (int j = 0; j < 4; j++) {
        v[j] = wg[lane + 32 * j];
        mn = fminf(mn, v[j]);
        mx = fmaxf(mx, v[j]);
    }
#pragma unroll
    for (int off = 16; off > 0; off >>= 1) {
        mn = fminf(mn, __shfl_xor_sync(0xffffffffu, mn, off));
        mx = fmaxf(mx, __shfl_xor_sync(0xffffffffu, mx, off));
    }
    float sc = __fdiv_rn(mx - mn, 15.0f);
    if (!(sc > 0.0f)) sc = 1.0f;
    float z = -8.0f - rintf(__fdiv_rn(mn, sc));

    __half* outp = g_WB + (size_t)g * 128;
#pragma unroll
    for (int j = 0; j < 4; j++) {
        float q = rintf(__fdiv_rn(v[j], sc)) + z;
        q = fminf(fmaxf(q, -8.0f), 7.0f);
        outp[lane + 32 * j] = __float2half_rn((q - z) * sc);
    }
}

// ============================================================
// Kernel 2: activation dynamic per-row int8 quant.
// Stores a = (q - z) exactly in fp16 (|a| <= 255), scale in g_SX.
// ============================================================
__global__ void __launch_bounds__(256) act_quant_kernel(const float* __restrict__ x) {
    int row = blockIdx.x;
    int tid = threadIdx.x;
    const float* xr = x + (size_t)row * KDIM;

    float vals[16];
    float mn = 3.4e38f, mx = -3.4e38f;
#pragma unroll
    for (int j = 0; j < 16; j++) {
        float v = xr[tid + j * 256];
        vals[j] = v;
        mn = fminf(mn, v);
        mx = fmaxf(mx, v);
    }
#pragma unroll
    for (int off = 16; off > 0; off >>= 1) {
        mn = fminf(mn, __shfl_xor_sync(0xffffffffu, mn, off));
        mx = fmaxf(mx, __shfl_xor_sync(0xffffffffu, mx, off));
    }
    __shared__ float smin[8], smax[8];
    __shared__ float s_sc, s_z;
    if ((tid & 31) == 0) { smin[tid >> 5] = mn; smax[tid >> 5] = mx; }
    __syncthreads();
    if (tid == 0) {
        float rmn = smin[0], rmx = smax[0];
#pragma unroll
        for (int i = 1; i < 8; i++) { rmn = fminf(rmn, smin[i]); rmx = fmaxf(rmx, smax[i]); }
        float sc = __fdiv_rn(rmx - rmn, 255.0f);
        if (!(sc > 0.0f)) sc = 1.0f;
        float z = -128.0f - rintf(__fdiv_rn(rmn, sc));
        s_sc = sc; s_z = z;
        g_SX[row] = sc;
    }
    __syncthreads();
    float sc = s_sc, z = s_z;
    __half* outp = g_XA + (size_t)row * KDIM;
#pragma unroll
    for (int j = 0; j < 16; j++) {
        float q = rintf(__fdiv_rn(vals[j], sc)) + z;
        q = fminf(fmaxf(q, -128.0f), 127.0f);
        outp[tid + j * 256] = __float2half_rn(q - z);  // exact integer in fp16
    }
}

// ============================================================
// Kernel 3: mma.sync fp16 GEMM (legacy HMMA path)
//   out[m, n] = SX[m] * sum_k XA[m,k] * WB[n,k]
// CTA tile 128x256, 16 warps (2x8), warp tile 64x32.
// 4-stage cp.async pipeline, SW128 XOR swizzle, ldmatrix.x4 loads.
// ============================================================
__global__ void __launch_bounds__(THREADS, 1)
gemm_kernel(float* __restrict__ out) {
    extern __shared__ char smem[];
    const uint32_t data = smem_u32(smem);

    const int tid  = threadIdx.x;
    const int wid  = tid >> 5;
    const int lane = tid & 31;
    const int wm   = wid & 1;        // 0..1  (M)
    const int wn   = wid >> 1;       // 0..7  (N)

    const int m0 = blockIdx.y * TM;
    const int n0 = blockIdx.x * TN;

    // ---------- producer addressing ----------
    // thread -> (row r0 = tid>>3 in 0..63, 16B chunk c = tid&7)
    const int  r0  = tid >> 3;
    const int  c   = tid & 7;
    const uint32_t swz = (uint32_t)(((c ^ (r0 & 7)) & 7) * 16);

    const char* gA = (const char*)g_XA + (size_t)(m0 + r0) * (KDIM * 2) + c * 16;
    const char* gB = (const char*)g_WB + (size_t)(n0 + r0) * (KDIM * 2) + c * 16;
    const uint32_t smA = data + (uint32_t)r0 * 128 + swz;
    const uint32_t smB = data + A_BYTES + (uint32_t)r0 * 128 + swz;

    // ---------- consumer (ldmatrix) addressing ----------
    // A x4 (m16k16), mf = 0..3: lanes 0-15 -> rows 0-15 col +0,
    // lanes 16-31 -> rows 0-15 col +16B => mats {m0-7/k0-7, m8-15/k0-7, m0-7/k8+, m8-15/k8+}
    uint32_t adA[4];  uint32_t axr[4];
#pragma unroll
    for (int mf = 0; mf < 4; mf++) {
        int r = wm * 64 + mf * 16 + (lane & 15);
        adA[mf] = data + (uint32_t)r * 128;
        axr[mf] = (uint32_t)((r & 7) * 16);
    }
    const uint32_t acol0 = (uint32_t)((lane >> 4) * 16);

    // B x4 covers n-frags {2g, 2g+1}: lanes 0-7 n0-7/k0-7, 8-15 n0-7/k8-15,
    // 16-23 n8-15/k0-7, 24-31 n8-15/k8-15
    uint32_t adB[2]; uint32_t bxr[2];
#pragma unroll
    for (int g = 0; g < 2; g++) {
        int r = wn * 32 + g * 16 + (lane & 7) + ((lane >> 4) * 8);
        adB[g] = data + A_BYTES + (uint32_t)r * 128;
        bxr[g] = (uint32_t)((r & 7) * 16);
    }
    const uint32_t bcol0 = (uint32_t)(((lane >> 3) & 1) * 16);

    float acc[4][4][4];
#pragma unroll
    for (int i = 0; i < 4; i++)
#pragma unroll
        for (int j = 0; j < 4; j++)
#pragma unroll
            for (int q = 0; q < 4; q++) acc[i][j][q] = 0.0f;

    // ---------- prologue ----------
    LOAD_STAGE(0);
    LOAD_STAGE(1);
    LOAD_STAGE(2);

    // ---------- main loop ----------
    for (int kb = 0; kb < NKB; kb++) {
        CP_WAIT2();
        __syncthreads();
        if (kb + NSTAGES - 1 < NKB) LOAD_STAGE(kb + NSTAGES - 1);

        const uint32_t so = (uint32_t)(kb & (NSTAGES - 1)) * STAGE_BYTES;
#pragma unroll
        for (int ks = 0; ks < 4; ks++) {
            const uint32_t kc = (uint32_t)(ks * 32);
            uint32_t a[4][4];
#pragma unroll
            for (int mf = 0; mf < 4; mf++)
                LDSM_X4(a[mf][0], a[mf][1], a[mf][2], a[mf][3],
                        adA[mf] + so + ((acol0 + kc) ^ axr[mf]));
            uint32_t b[4][2];
#pragma unroll
            for (int g = 0; g < 2; g++)
                LDSM_X4(b[2 * g][0], b[2 * g][1], b[2 * g + 1][0], b[2 * g + 1][1],
                        adB[g] + so + ((bcol0 + kc) ^ bxr[g]));
#pragma unroll
            for (int mf = 0; mf < 4; mf++)
#pragma unroll
                for (int nf = 0; nf < 4; nf++)
                    MMA16816(acc[mf][nf], a[mf], b[nf]);
        }
        __syncthreads();
    }
    CP_WAIT0();

    // ---------- epilogue: scale by sx[m], store float2 ----------
#pragma unroll
    for (int mf = 0; mf < 4; mf++) {
        const int m_lo = m0 + wm * 64 + mf * 16 + (lane >> 2);
        const int m_hi = m_lo + 8;
        const float sx0 = g_SX[m_lo];
        const float sx1 = g_SX[m_hi];
        float* row_lo = out + (size_t)m_lo * NDIM + n0 + wn * 32 + (lane & 3) * 2;
        float* row_hi = out + (size_t)m_hi * NDIM + n0 + wn * 32 + (lane & 3) * 2;
#pragma unroll
        for (int nf = 0; nf < 4; nf++) {
            float2 v0 = make_float2(acc[mf][nf][0] * sx0, acc[mf][nf][1] * sx0);
            float2 v1 = make_float2(acc[mf][nf][2] * sx1, acc[mf][nf][3] * sx1);
            *(float2*)(row_lo + nf * 8) = v0;
            *(float2*)(row_hi + nf * 8) = v1;
        }
    }
}

// ============================================================
// Launcher
// ============================================================
extern "C" void kernel_launch(void* const* d_in, const int* in_sizes, int n_in,
                              void* d_out, int out_size) {
    const float* x = (const float*)d_in[0];   // [4, 2048, 4096] fp32
    const float* w = (const float*)d_in[1];   // [4096, 4096] fp32
    float* out = (float*)d_out;               // [4, 2048, 4096] fp32

    cudaFuncSetAttribute(gemm_kernel, cudaFuncAttributeMaxDynamicSharedMemorySize, GEMM_SMEM);

    w_quant_kernel<<<16384, 256>>>(w);        // 131072 groups / 8 per block
    act_quant_kernel<<<MROWS, 256>>>(x);
    gemm_kernel<<<dim3(NDIM / TN, MROWS / TM), THREADS, GEMM_SMEM>>>(out);
}

// round 5
// speedup vs baseline: 1.2679x; 1.2679x over previous
#include <cuda_runtime.h>
#include <cstdint>
#include <cstddef>

// ============================================================
// Problem dims (fixed)
// ============================================================
#define MROWS 8192
#define NDIM  4096
#define KDIM  4096
#define KGROUPS 32                   // 4096 / 128 quant groups per row

// GEMM tiling: CTA 128x128, 8 warps (2 M x 4 N), warp tile 64x32
#define TM 128
#define TN 128
#define KB 128                       // K int8 per stage = 128 B per row = ONE quant group
#define NKB (KDIM / KB)              // 32
#define NSTAGES 4
#define A_BYTES (TM * 128)           // 16384
#define B_BYTES (TN * 128)           // 16384
#define STAGE_BYTES (A_BYTES + B_BYTES)            // 32768
#define SW_BYTES (KGROUPS * TN * 4)                // 16384 group scales staged in SMEM
#define GEMM_SMEM (SW_BYTES + NSTAGES * STAGE_BYTES)   // 147456

#define THREADS 256

// ============================================================
// Scratch (static __device__ — no runtime allocation)
// ============================================================
__device__ signed char g_XQ[(size_t)MROWS * KDIM];   // 32 MB: qx int8 (exact)
__device__ signed char g_WQ[(size_t)NDIM * KDIM];    // 16 MB: wq = (q - z) in [0,15]
__device__ float g_SX[MROWS];                        // activation scale per row
__device__ float g_ZX[MROWS];                        // activation zero per row
__device__ float g_WS[(size_t)NDIM * KGROUPS];       // weight group scale sw[n][g]
__device__ float g_WGS[(size_t)NDIM * KGROUPS];      // sw[n][g] * sum_{k in g} wq
__device__ float g_WSUM[NDIM];                       // sum_k w_deq[n][k]

// ============================================================
// PTX helpers (sm_100 baseline ISA — no 'a'-suffix features)
// ============================================================
__device__ __forceinline__ uint32_t smem_u32(const void* p) {
    uint32_t a;
    asm("{ .reg .u64 t; cvta.to.shared.u64 t, %1; cvt.u32.u64 %0, t; }" : "=r"(a) : "l"(p));
    return a;
}

#define CP16(smem_addr, gptr) \
    asm volatile("cp.async.cg.shared.global [%0], [%1], 16;" :: "r"(smem_addr), "l"(gptr) : "memory")
#define CP_COMMIT()  asm volatile("cp.async.commit_group;" ::: "memory")
#define CP_WAIT2()   asm volatile("cp.async.wait_group 2;" ::: "memory")
#define CP_WAIT0()   asm volatile("cp.async.wait_group 0;" ::: "memory")

#define LDSM_X4(r0, r1, r2, r3, addr)                                        \
    asm volatile("ldmatrix.sync.aligned.m8n8.x4.shared.b16 {%0,%1,%2,%3}, [%4];" \
                 : "=r"(r0), "=r"(r1), "=r"(r2), "=r"(r3) : "r"(addr))

#define MMAS8(c, a, b0, b1)                                                  \
    asm volatile("mma.sync.aligned.m16n8k32.row.col.s32.s8.s8.s32 "          \
                 "{%0,%1,%2,%3}, {%4,%5,%6,%7}, {%8,%9}, {%0,%1,%2,%3};"     \
                 : "+r"((c)[0]), "+r"((c)[1]), "+r"((c)[2]), "+r"((c)[3])    \
                 : "r"((a)[0]), "r"((a)[1]), "r"((a)[2]), "r"((a)[3]),       \
                   "r"((b0)), "r"((b1)))

// Stage load: A rows {r0,+32,+64,+96}, B rows same; one 16B chunk per row per thread.
#define LOAD_STAGE(kb)                                                        \
    do {                                                                      \
        const uint32_t so = (uint32_t)((kb) & (NSTAGES - 1)) * STAGE_BYTES;   \
        const signed char* pA = gA + (size_t)(kb) * 128;                      \
        const signed char* pB = gB + (size_t)(kb) * 128;                      \
        CP16(smA + so,            pA);                                        \
        CP16(smA + so + 32 * 128, pA + (size_t)32 * KDIM);                    \
        CP16(smA + so + 64 * 128, pA + (size_t)64 * KDIM);                    \
        CP16(smA + so + 96 * 128, pA + (size_t)96 * KDIM);                    \
        CP16(smB + so,            pB);                                        \
        CP16(smB + so + 32 * 128, pB + (size_t)32 * KDIM);                    \
        CP16(smB + so + 64 * 128, pB + (size_t)64 * KDIM);                    \
        CP16(smB + so + 96 * 128, pB + (size_t)96 * KDIM);                    \
        CP_COMMIT();                                                          \
    } while (0)

// ============================================================
// Kernel 1: weight group quant (gs=128, nbit=4, asym) -> int8 wq + scales
// scale=(max-min)/15, z=-8-rint(min/s), q=clip(rint(w/s)+z,-8,7), wq=q-z in [0,15]
// ============================================================
__global__ void __launch_bounds__(256) w_quant_kernel(const float* __restrict__ w) {
    int g    = blockIdx.x * 8 + (threadIdx.x >> 5);   // global group id = n*32 + gk
    int lane = threadIdx.x & 31;
    const float* wg = w + (size_t)g * 128;

    float v[4];
    float mn = 3.4e38f, mx = -3.4e38f;
#pragma unroll
    for (int j = 0; j < 4; j++) {
        v[j] = wg[lane + 32 * j];
        mn = fminf(mn, v[j]);
        mx = fmaxf(mx, v[j]);
    }
#pragma unroll
    for (int off = 16; off > 0; off >>= 1) {
        mn = fminf(mn, __shfl_xor_sync(0xffffffffu, mn, off));
        mx = fmaxf(mx, __shfl_xor_sync(0xffffffffu, mx, off));
    }
    float sc = __fdiv_rn(mx - mn, 15.0f);
    if (!(sc > 0.0f)) sc = 1.0f;
    float z = -8.0f - rintf(__fdiv_rn(mn, sc));

    signed char* outp = g_WQ + (size_t)g * 128;
    float gsum = 0.0f;
#pragma unroll
    for (int j = 0; j < 4; j++) {
        float q = rintf(__fdiv_rn(v[j], sc)) + z;
        q = fminf(fmaxf(q, -8.0f), 7.0f);
        float wq = q - z;                 // exact small integer in [0,15]
        gsum += wq;
        outp[lane + 32 * j] = (signed char)__float2int_rn(wq);
    }
#pragma unroll
    for (int off = 16; off > 0; off >>= 1)
        gsum += __shfl_xor_sync(0xffffffffu, gsum, off);
    if (lane == 0) {
        g_WS[g]  = sc;
        g_WGS[g] = sc * gsum;             // sw * sum(wq) for this group
    }
}

// ============================================================
// Kernel 1b: WSUM[n] = sum_g g_WGS[n*32+g]  (one warp per n-row)
// ============================================================
__global__ void __launch_bounds__(256) wsum_kernel() {
    int n    = blockIdx.x * 8 + (threadIdx.x >> 5);
    int lane = threadIdx.x & 31;
    float v = g_WGS[(size_t)n * KGROUPS + lane];      // KGROUPS == 32 == warp size
#pragma unroll
    for (int off = 16; off > 0; off >>= 1)
        v += __shfl_xor_sync(0xffffffffu, v, off);
    if (lane == 0) g_WSUM[n] = v;
}

// ============================================================
// Kernel 2: activation dynamic per-row int8 quant -> qx int8, sx, zx
// ============================================================
__global__ void __launch_bounds__(256) act_quant_kernel(const float* __restrict__ x) {
    int row = blockIdx.x;
    int tid = threadIdx.x;
    const float* xr = x + (size_t)row * KDIM;

    float vals[16];
    float mn = 3.4e38f, mx = -3.4e38f;
#pragma unroll
    for (int j = 0; j < 16; j++) {
        float v = xr[tid + j * 256];
        vals[j] = v;
        mn = fminf(mn, v);
        mx = fmaxf(mx, v);
    }
#pragma unroll
    for (int off = 16; off > 0; off >>= 1) {
        mn = fminf(mn, __shfl_xor_sync(0xffffffffu, mn, off));
        mx = fmaxf(mx, __shfl_xor_sync(0xffffffffu, mx, off));
    }
    __shared__ float smin[8], smax[8];
    __shared__ float s_sc, s_z;
    if ((tid & 31) == 0) { smin[tid >> 5] = mn; smax[tid >> 5] = mx; }
    __syncthreads();
    if (tid == 0) {
        float rmn = smin[0], rmx = smax[0];
#pragma unroll
        for (int i = 1; i < 8; i++) { rmn = fminf(rmn, smin[i]); rmx = fmaxf(rmx, smax[i]); }
        float sc = __fdiv_rn(rmx - rmn, 255.0f);
        if (!(sc > 0.0f)) sc = 1.0f;
        float z = -128.0f - rintf(__fdiv_rn(rmn, sc));
        s_sc = sc; s_z = z;
        g_SX[row] = sc;
        g_ZX[row] = z;
    }
    __syncthreads();
    float sc = s_sc, z = s_z;
    signed char* outp = g_XQ + (size_t)row * KDIM;
#pragma unroll
    for (int j = 0; j < 16; j++) {
        float q = rintf(__fdiv_rn(vals[j], sc)) + z;
        q = fminf(fmaxf(q, -128.0f), 127.0f);
        outp[tid + j * 256] = (signed char)__float2int_rn(q);
    }
}

// ============================================================
// Kernel 3: int8 IMMA GEMM with per-group scale folding
//   y[m,n] = sx_m * ( sum_g sw[n,g] * S1_g[m,n] ) - sx_m*zx_m*WSUM[n]
//   S1_g exact int32 (|.| < 2^24 -> exact I2F).
// CTA 128x128, 8 warps (2x4), warp tile 64x32; K-stage = 1 group (128 int8).
// ============================================================
__global__ void __launch_bounds__(THREADS, 1)
gemm_kernel(float* __restrict__ out) {
    extern __shared__ char smem[];
    const uint32_t swbase = smem_u32(smem);          // [32 g][128 n] fp32 = 16 KB
    const uint32_t tiles  = swbase + SW_BYTES;

    const int tid  = threadIdx.x;
    const int wid  = tid >> 5;
    const int lane = tid & 31;
    const int wm   = wid & 1;        // 0..1  (M)
    const int wn   = wid >> 1;       // 0..3  (N)

    const int m0 = blockIdx.y * TM;
    const int n0 = blockIdx.x * TN;

    // ---------- producer addressing ----------
    const int  r0  = tid >> 3;       // 0..31
    const int  c   = tid & 7;        // 16B chunk within 128B row
    const uint32_t swz = (uint32_t)(((c ^ (r0 & 7)) & 7) * 16);

    const signed char* gA = g_XQ + (size_t)(m0 + r0) * KDIM + c * 16;
    const signed char* gB = g_WQ + (size_t)(n0 + r0) * KDIM + c * 16;
    const uint32_t smA = tiles + (uint32_t)r0 * 128 + swz;
    const uint32_t smB = tiles + A_BYTES + (uint32_t)r0 * 128 + swz;

    // ---------- stage the group scales: sw_s[g][n] = g_WS[(n0+n)*32 + g] ----------
    for (int idx = tid; idx < KGROUPS * TN; idx += THREADS) {
        int n = idx >> 5;            // 0..127  (g contiguous in global -> coalesced LDG)
        int g = idx & 31;
        ((float*)smem)[g * TN + n] = g_WS[(size_t)(n0 + n) * KGROUPS + g];
    }

    // ---------- consumer (ldmatrix) addressing ----------
    // swizzle XOR term: row&7 == lane&7 for all fragment rows used below
    const uint32_t xr = (uint32_t)((lane & 7) * 16);
    // A x4 tiles (m16 x k32): rows mf*16 + (lane&7) + ((lane>>3)&1)*8; chunk (lane>>4)*16
    const uint32_t adA0 = tiles +
        (uint32_t)(wm * 64 + (lane & 7) + ((lane >> 3) & 1) * 8) * 128;
    const uint32_t ach = (uint32_t)((lane >> 4) * 16);
    // B x4 tiles (2 n-frags x k32): rows g*16 + (lane&7) + (lane>>4)*8; chunk ((lane>>3)&1)*16
    const uint32_t adB0 = tiles + A_BYTES +
        (uint32_t)(wn * 32 + (lane & 7) + (lane >> 4) * 8) * 128;
    const uint32_t bch = (uint32_t)(((lane >> 3) & 1) * 16);

    float facc[4][4][4];
#pragma unroll
    for (int i = 0; i < 4; i++)
#pragma unroll
        for (int j = 0; j < 4; j++)
#pragma unroll
            for (int q = 0; q < 4; q++) facc[i][j][q] = 0.0f;

    // per-thread n columns for scale folding: nloc_even = wn*32 + nf*8 + (lane&3)*2
    const int ncol2 = (lane & 3) * 2;

    // ---------- prologue ----------
    LOAD_STAGE(0);
    LOAD_STAGE(1);
    LOAD_STAGE(2);

    // ---------- main loop: one quant group per iteration ----------
    for (int kb = 0; kb < NKB; kb++) {
        CP_WAIT2();
        __syncthreads();
        if (kb + NSTAGES - 1 < NKB) LOAD_STAGE(kb + NSTAGES - 1);

        const uint32_t so = (uint32_t)(kb & (NSTAGES - 1)) * STAGE_BYTES;

        // group scales for this thread's 8 n-columns
        float swr[8];
#pragma unroll
        for (int nf = 0; nf < 4; nf++) {
            float2 s2 = *(const float2*)(smem + (size_t)kb * TN * 4 +
                                         (size_t)(wn * 32 + nf * 8 + ncol2) * 4);
            swr[2 * nf]     = s2.x;
            swr[2 * nf + 1] = s2.y;
        }

        // preload all B fragments for this stage: bu[ks][nf*2 + {0,1}]
        uint32_t bu[4][8];
#pragma unroll
        for (int ks = 0; ks < 4; ks++) {
            const uint32_t kc = (uint32_t)(ks * 32);
            LDSM_X4(bu[ks][0], bu[ks][1], bu[ks][2], bu[ks][3],
                    adB0 + so + ((kc + bch) ^ xr));
            LDSM_X4(bu[ks][4], bu[ks][5], bu[ks][6], bu[ks][7],
                    adB0 + 2048 + so + ((kc + bch) ^ xr));
        }

#pragma unroll
        for (int mf = 0; mf < 4; mf++) {
            int ic[4][4];
#pragma unroll
            for (int nf = 0; nf < 4; nf++)
#pragma unroll
                for (int q = 0; q < 4; q++) ic[nf][q] = 0;

#pragma unroll
            for (int ks = 0; ks < 4; ks++) {
                const uint32_t kc = (uint32_t)(ks * 32);
                uint32_t a[4];
                LDSM_X4(a[0], a[1], a[2], a[3],
                        adA0 + (uint32_t)mf * 2048 + so + ((kc + ach) ^ xr));
#pragma unroll
                for (int nf = 0; nf < 4; nf++)
                    MMAS8(ic[nf], a, bu[ks][2 * nf], bu[ks][2 * nf + 1]);
            }
            // fold group: facc += sw * S1  (I2F exact: |S1| < 2^24)
#pragma unroll
            for (int nf = 0; nf < 4; nf++) {
                facc[mf][nf][0] += __int2float_rn(ic[nf][0]) * swr[2 * nf];
                facc[mf][nf][1] += __int2float_rn(ic[nf][1]) * swr[2 * nf + 1];
                facc[mf][nf][2] += __int2float_rn(ic[nf][2]) * swr[2 * nf];
                facc[mf][nf][3] += __int2float_rn(ic[nf][3]) * swr[2 * nf + 1];
            }
        }
        __syncthreads();
    }
    CP_WAIT0();

    // ---------- epilogue: y = sx*(facc - zx*WSUM[n]) ----------
#pragma unroll
    for (int mf = 0; mf < 4; mf++) {
        const int m_lo = m0 + wm * 64 + mf * 16 + (lane >> 2);
        const int m_hi = m_lo + 8;
        const float sx0 = g_SX[m_lo], zx0 = g_ZX[m_lo];
        const float sx1 = g_SX[m_hi], zx1 = g_ZX[m_hi];
        float* row_lo = out + (size_t)m_lo * NDIM + n0 + wn * 32 + ncol2;
        float* row_hi = out + (size_t)m_hi * NDIM + n0 + wn * 32 + ncol2;
#pragma unroll
        for (int nf = 0; nf < 4; nf++) {
            const int ng = n0 + wn * 32 + nf * 8 + ncol2;
            const float ws0 = g_WSUM[ng];
            const float ws1 = g_WSUM[ng + 1];
            float2 v0, v1;
            v0.x = sx0 * (facc[mf][nf][0] - zx0 * ws0);
            v0.y = sx0 * (facc[mf][nf][1] - zx0 * ws1);
            v1.x = sx1 * (facc[mf][nf][2] - zx1 * ws0);
            v1.y = sx1 * (facc[mf][nf][3] - zx1 * ws1);
            *(float2*)(row_lo + nf * 8) = v0;
            *(float2*)(row_hi + nf * 8) = v1;
        }
    }
}

// ============================================================
// Launcher
// ============================================================
extern "C" void kernel_launch(void* const* d_in, const int* in_sizes, int n_in,
                              void* d_out, int out_size) {
    const float* x = (const float*)d_in[0];   // [4, 2048, 4096] fp32
    const float* w = (const float*)d_in[1];   // [4096, 4096] fp32
    float* out = (float*)d_out;               // [4, 2048, 4096] fp32

    cudaFuncSetAttribute(gemm_kernel, cudaFuncAttributeMaxDynamicSharedMemorySize, GEMM_SMEM);

    w_quant_kernel<<<16384, 256>>>(w);        // 131072 groups / 8 per block
    wsum_kernel<<<512, 256>>>();              // 4096 rows / 8 per block
    act_quant_kernel<<<MROWS, 256>>>(x);
    gemm_kernel<<<dim3(NDIM / TN, MROWS / TM), THREADS, GEMM_SMEM>>>(out);
}